// round 2
// baseline (speedup 1.0000x reference)
#include <cuda_runtime.h>
#include <cstdint>

#define NPROP 8192
#define HID   512

// ---------------- scratch (static device arrays; no runtime alloc) ----------
__device__ float g_conv [(size_t)NPROP * 512];      // conv output, padded 504->512
__device__ float g_feats[(size_t)NPROP * 512];
__device__ float g_Gi   [(size_t)NPROP * 1536];     // reused for encoder then decoder
__device__ float g_hs   [(size_t)NPROP * 512];      // h_{t+1} per step (also bcast medium)
__device__ float g_decin[(size_t)NPROP * 512];
__device__ float g_WaxPad[512 * 512];               // W_axis padded 504 -> 512 cols
__device__ unsigned g_tags[32];

// ---------------- helpers ---------------------------------------------------
__device__ __forceinline__ void fma2(unsigned long long& acc, unsigned long long a,
                                     unsigned long long b) {
    asm("fma.rn.f32x2 %0, %1, %2, %0;" : "+l"(acc) : "l"(a), "l"(b));
}
__device__ __forceinline__ float2 unpack2(unsigned long long v) {
    float2 r; asm("mov.b64 {%0,%1}, %2;" : "=f"(r.x), "=f"(r.y) : "l"(v)); return r;
}
__device__ __forceinline__ float sigm(float x) { return 1.f / (1.f + __expf(-x)); }
__device__ __forceinline__ float tanh_acc(float x) {
    float ax = fabsf(x);
    float e  = __expf(-2.f * ax);
    return copysignf((1.f - e) / (1.f + e), x);
}

// ---------------- conv: [N,81,4,4] (x) [56,81,2,2] -> [N,504] (+pad to 512) --
__global__ void conv_kernel(const float* __restrict__ x, const float* __restrict__ Wc,
                            const float* __restrict__ bc) {
    __shared__ float xs[1296];
    const int n = blockIdx.x;
    const float4* xp = (const float4*)(x + (size_t)n * 1296);
    for (int i = threadIdx.x; i < 324; i += 64) ((float4*)xs)[i] = xp[i];
    __syncthreads();
    const int o = threadIdx.x;
    if (o < 56) {
        float acc[9];
        const float b = bc[o];
        #pragma unroll
        for (int p = 0; p < 9; p++) acc[p] = b;
        for (int i = 0; i < 81; i++) {
            float4 wv = *(const float4*)(Wc + o * 324 + i * 4);
            const float* xi = xs + i * 16;
            #pragma unroll
            for (int py = 0; py < 3; py++)
                #pragma unroll
                for (int px = 0; px < 3; px++) {
                    int p = py * 3 + px;
                    acc[p] += xi[py * 4 + px]     * wv.x + xi[py * 4 + px + 1]     * wv.y
                            + xi[(py+1) * 4 + px] * wv.z + xi[(py+1) * 4 + px + 1] * wv.w;
                }
        }
        float* op = g_conv + (size_t)n * 512 + o * 9;
        #pragma unroll
        for (int p = 0; p < 9; p++) op[p] = acc[p];
    } else {                       // threads 56..63 zero padded cols 504..511
        g_conv[(size_t)n * 512 + 448 + o] = 0.f;
    }
}

// ---------------- pad W_axis [512,504] -> [512,512] --------------------------
__global__ void pad_waxis(const float* __restrict__ W) {
    int idx = blockIdx.x * 256 + threadIdx.x;          // 512*512 = 262144
    int r = idx >> 9, c = idx & 511;
    g_WaxPad[idx] = (c < 504) ? W[r * 504 + c] : 0.f;
}

// ---------------- SGEMM: C[M,N] (+)= A[M,K] * B[N,K]^T + bias[N] -------------
template <int ACC>
__global__ __launch_bounds__(256)
void sgemm_nt(const float* __restrict__ A, const float* __restrict__ B,
              const float* __restrict__ bias, float* __restrict__ C,
              int M, int N, int K) {
    __shared__ float As[8][128];
    __shared__ float Bs[8][128];
    const int tid = threadIdx.x;
    const int tx = tid & 15, ty = tid >> 4;
    const int lr = tid >> 1;
    const int lc = (tid & 1) << 2;
    const float* Ap = A + (size_t)(blockIdx.y * 128 + lr) * K + lc;
    const float* Bp = B + (size_t)(blockIdx.x * 128 + lr) * K + lc;
    float acc[8][8] = {};
    for (int k0 = 0; k0 < K; k0 += 8) {
        float4 av = *(const float4*)(Ap + k0);
        float4 bv = *(const float4*)(Bp + k0);
        __syncthreads();
        As[lc+0][lr] = av.x; As[lc+1][lr] = av.y; As[lc+2][lr] = av.z; As[lc+3][lr] = av.w;
        Bs[lc+0][lr] = bv.x; Bs[lc+1][lr] = bv.y; Bs[lc+2][lr] = bv.z; Bs[lc+3][lr] = bv.w;
        __syncthreads();
        #pragma unroll
        for (int k = 0; k < 8; k++) {
            float af[8], bf[8];
            *(float4*)(af)     = *(const float4*)&As[k][ty * 8];
            *(float4*)(af + 4) = *(const float4*)&As[k][ty * 8 + 4];
            *(float4*)(bf)     = *(const float4*)&Bs[k][tx * 8];
            *(float4*)(bf + 4) = *(const float4*)&Bs[k][tx * 8 + 4];
            #pragma unroll
            for (int i = 0; i < 8; i++)
                #pragma unroll
                for (int j = 0; j < 8; j++)
                    acc[i][j] += af[i] * bf[j];
        }
    }
    const int row0 = blockIdx.y * 128 + ty * 8;
    const int col0 = blockIdx.x * 128 + tx * 8;
    float bvals[8];
    #pragma unroll
    for (int j = 0; j < 8; j++) bvals[j] = bias[col0 + j];
    #pragma unroll
    for (int i = 0; i < 8; i++) {
        float* cp = C + (size_t)(row0 + i) * N + col0;
        #pragma unroll
        for (int j = 0; j < 8; j += 4) {
            float4 v;
            v.x = acc[i][j+0] + bvals[j+0];
            v.y = acc[i][j+1] + bvals[j+1];
            v.z = acc[i][j+2] + bvals[j+2];
            v.w = acc[i][j+3] + bvals[j+3];
            if (ACC) {
                float4 o = *(const float4*)(cp + j);
                v.x += o.x; v.y += o.y; v.z += o.z; v.w += o.w;
            }
            *(float4*)(cp + j) = v;
        }
    }
}

// ---------------- init tags --------------------------------------------------
__global__ void init_tags() { g_tags[threadIdx.x] = 0u; }

// ---------------- persistent GRU scan ----------------------------------------
// 32 CTAs x 192 threads. CTA c owns h[c*16 .. c*16+15] and the 48 Whh rows
// {g*512 + c*16 + j : g in {r,z,n}, j in [0,16)}. Weights live in registers
// (64 packed f32x2 per thread). h broadcast via g_hs[t] + release/acquire tags.
__global__ __launch_bounds__(192, 1)
void scan_kernel(const float* __restrict__ Whh, const float* __restrict__ bhh, int steps) {
    __shared__ float hsm[4 * 516];     // 4 bank-padded copies of h
    __shared__ float gh_s[48];
    const int c   = blockIdx.x;
    const int tid = threadIdx.x;
    const int w   = tid >> 5;
    const int l   = tid & 31;
    const int q   = w * 8 + (l >> 2);  // local row 0..47
    const int seg = l & 3;             // k-segment 0..3 (128 floats each)
    const int gate = q >> 4, j = q & 15;
    const int grow = gate * 512 + c * 16 + j;

    unsigned long long wq[64];
    {
        const ulonglong2* wp = (const ulonglong2*)(Whh + (size_t)grow * 512 + seg * 128);
        #pragma unroll
        for (int i = 0; i < 32; i++) { ulonglong2 t2 = wp[i]; wq[2*i] = t2.x; wq[2*i+1] = t2.y; }
    }
    const float bh = bhh[grow];

    for (int i = tid; i < 4 * 516; i += 192) hsm[i] = 0.f;   // h_0 = 0
    float hreg = 0.f;
    __syncthreads();

    // copy #seg of h, at this segment's 128-float window
    const float* hseg = hsm + seg * 516 + seg * 128;

    for (int t = 0; t < steps; t++) {
        // prefetch input gates (independent of h) early
        float gi_r = 0.f, gi_z = 0.f, gi_n = 0.f;
        if (w == 0 && l < 16) {
            const float* g = g_Gi + (size_t)t * 1536 + c * 16 + l;
            gi_r = __ldcs(g); gi_z = __ldcs(g + 512); gi_n = __ldcs(g + 1024);
        }
        // GEMV: dot(Whh[grow, seg*128 : seg*128+128], h[seg*128 : seg*128+128])
        unsigned long long a0 = 0ull, a1 = 0ull;
        #pragma unroll
        for (int i = 0; i < 32; i++) {
            ulonglong2 hv = *(const ulonglong2*)(hseg + i * 4);
            fma2(a0, wq[2*i],   hv.x);
            fma2(a1, wq[2*i+1], hv.y);
        }
        float2 f0 = unpack2(a0), f1 = unpack2(a1);
        float v = (f0.x + f0.y) + (f1.x + f1.y);
        v += __shfl_xor_sync(0xffffffffu, v, 1);
        v += __shfl_xor_sync(0xffffffffu, v, 2);
        if (seg == 0) gh_s[q] = v + bh;
        __syncthreads();                                  // (1) gh ready

        // activations + publish (warp 0, lanes 0..15)
        if (w == 0 && l < 16) {
            float r  = sigm(gi_r + gh_s[l]);
            float z  = sigm(gi_z + gh_s[16 + l]);
            float n  = tanh_acc(gi_n + r * gh_s[32 + l]);
            hreg = (1.f - z) * n + z * hreg;
            g_hs[(size_t)t * 512 + c * 16 + l] = hreg;
            __syncwarp(0x0000ffffu);
            if (l == 0) {
                __threadfence();
                asm volatile("st.global.release.gpu.u32 [%0], %1;"
                             :: "l"(g_tags + c), "r"(t + 1) : "memory");
            }
        }
        // poll all 32 tags (warp 5)
        if (w == 5 && (t + 1) < steps) {
            unsigned tg;
            do {
                asm volatile("ld.global.acquire.gpu.u32 %0, [%1];"
                             : "=r"(tg) : "l"(g_tags + l) : "memory");
            } while (__any_sync(0xffffffffu, tg < (unsigned)(t + 1)));
        }
        __syncthreads();                                  // (2) h_{t+1} globally visible

        if ((t + 1) < steps && tid < 128) {
            float4 hv = __ldcg((const float4*)(g_hs + (size_t)t * 512) + tid);
            #pragma unroll
            for (int cp = 0; cp < 4; cp++)
                *(float4*)(hsm + cp * 516 + tid * 4) = hv;
        }
        __syncthreads();                                  // (3) smem h refreshed
    }
}

// ---------------- decin = relu(feats + enc_final) ----------------------------
__global__ void decin_kernel() {
    int idx = blockIdx.x * 512 + threadIdx.x;            // 8192*128 float4s
    const float4* f4 = (const float4*)g_feats;
    const float4* e4 = (const float4*)(g_hs + (size_t)8191 * 512);
    float4 f = f4[idx];
    float4 e = e4[idx & 127];
    float4 r;
    r.x = fmaxf(f.x + e.x, 0.f); r.y = fmaxf(f.y + e.y, 0.f);
    r.z = fmaxf(f.z + e.z, 0.f); r.w = fmaxf(f.w + e.w, 0.f);
    ((float4*)g_decin)[idx] = r;
}

// ---------------- out = sigmoid(hs @ W_out^T + b_out) ------------------------
__global__ void out_kernel(const float* __restrict__ Wout, const float* __restrict__ bout,
                           float* __restrict__ out) {
    int row = blockIdx.x * 8 + (threadIdx.x >> 5);
    int l = threadIdx.x & 31;
    const float4* h4 = (const float4*)(g_hs + (size_t)row * 512);
    const float4* w4 = (const float4*)Wout;
    float s = 0.f;
    #pragma unroll
    for (int k = 0; k < 4; k++) {
        float4 h = h4[l + 32 * k], w = w4[l + 32 * k];
        s += h.x * w.x + h.y * w.y + h.z * w.z + h.w * w.w;
    }
    #pragma unroll
    for (int o = 16; o > 0; o >>= 1) s += __shfl_xor_sync(0xffffffffu, s, o);
    if (l == 0) out[row] = sigm(s + bout[0]);
}

// ---------------- launch ------------------------------------------------------
extern "C" void kernel_launch(void* const* d_in, const int* in_sizes, int n_in,
                              void* d_out, int out_size) {
    const float* boxes_feature   = (const float*)d_in[0];
    const float* boxes_box_score = (const float*)d_in[1];
    const float* W_app  = (const float*)d_in[2];
    const float* b_app  = (const float*)d_in[3];
    const float* W_conv = (const float*)d_in[4];
    const float* b_conv = (const float*)d_in[5];
    const float* W_axis = (const float*)d_in[6];
    const float* b_axis = (const float*)d_in[7];
    const float* Wih_e  = (const float*)d_in[8];
    const float* Whh_e  = (const float*)d_in[9];
    const float* bih_e  = (const float*)d_in[10];
    const float* bhh_e  = (const float*)d_in[11];
    const float* Wih_d  = (const float*)d_in[12];
    const float* Whh_d  = (const float*)d_in[13];
    const float* bih_d  = (const float*)d_in[14];
    const float* bhh_d  = (const float*)d_in[15];
    const float* W_out  = (const float*)d_in[16];
    const float* b_out  = (const float*)d_in[17];
    float* out = (float*)d_out;

    // feats = boxes_feature @ W_app^T + b_app + conv @ W_axis^T + b_axis
    conv_kernel<<<NPROP, 64>>>(boxes_box_score, W_conv, b_conv);
    pad_waxis<<<1024, 256>>>(W_axis);

    float* feats = nullptr; cudaGetSymbolAddress((void**)&feats, g_feats);
    float* convp = nullptr; cudaGetSymbolAddress((void**)&convp, g_conv);
    float* waxp  = nullptr; cudaGetSymbolAddress((void**)&waxp,  g_WaxPad);
    float* gi    = nullptr; cudaGetSymbolAddress((void**)&gi,    g_Gi);
    float* decin = nullptr; cudaGetSymbolAddress((void**)&decin, g_decin);

    sgemm_nt<0><<<dim3(4, 64), 256>>>(boxes_feature, W_app, b_app, feats, NPROP, 512, 1024);
    sgemm_nt<1><<<dim3(4, 64), 256>>>(convp, waxp, b_axis, feats, NPROP, 512, 512);

    // encoder
    sgemm_nt<0><<<dim3(12, 64), 256>>>(feats, Wih_e, bih_e, gi, NPROP, 1536, 512);
    init_tags<<<1, 32>>>();
    scan_kernel<<<32, 192>>>(Whh_e, bhh_e, NPROP);

    // decoder
    decin_kernel<<<2048, 512>>>();
    sgemm_nt<0><<<dim3(12, 64), 256>>>(decin, Wih_d, bih_d, gi, NPROP, 1536, 512);
    init_tags<<<1, 32>>>();
    scan_kernel<<<32, 192>>>(Whh_d, bhh_d, NPROP);

    out_kernel<<<1024, 256>>>(W_out, b_out, out);
}

// round 3
// speedup vs baseline: 1.4926x; 1.4926x over previous
#include <cuda_runtime.h>
#include <cstdint>

#define NPROP 8192
#define HID   512
#define NCTA  16          // cluster size for the scan
#define NTHR  384         // threads per scan CTA

// ---------------- scratch (static device arrays; no runtime alloc) ----------
__device__ float g_conv [(size_t)NPROP * 512];      // conv output, padded 504->512
__device__ float g_feats[(size_t)NPROP * 512];
__device__ float g_Gi   [(size_t)NPROP * 1536];     // reused for encoder then decoder
__device__ float g_hs   [(size_t)NPROP * 512];      // h_{t+1} per step
__device__ float g_decin[(size_t)NPROP * 512];
__device__ float g_WaxPad[512 * 512];               // W_axis padded 504 -> 512 cols

// ---------------- helpers ---------------------------------------------------
__device__ __forceinline__ void fma2(unsigned long long& acc, unsigned long long a,
                                     unsigned long long b) {
    asm("fma.rn.f32x2 %0, %1, %2, %0;" : "+l"(acc) : "l"(a), "l"(b));
}
__device__ __forceinline__ float2 unpack2(unsigned long long v) {
    float2 r; asm("mov.b64 {%0,%1}, %2;" : "=f"(r.x), "=f"(r.y) : "l"(v)); return r;
}
__device__ __forceinline__ float sigm(float x) { return 1.f / (1.f + __expf(-x)); }
__device__ __forceinline__ float tanh_acc(float x) {
    float ax = fabsf(x);
    float e  = __expf(-2.f * ax);
    return copysignf((1.f - e) / (1.f + e), x);
}
__device__ __forceinline__ uint32_t smem_u32(const void* p) {
    uint32_t a;
    asm("{ .reg .u64 t; cvta.to.shared.u64 t, %1; cvt.u32.u64 %0, t; }" : "=r"(a) : "l"(p));
    return a;
}
__device__ __forceinline__ uint32_t mapa_u32(uint32_t local, uint32_t rank) {
    uint32_t r;
    asm("mapa.shared::cluster.u32 %0, %1, %2;" : "=r"(r) : "r"(local), "r"(rank));
    return r;
}
__device__ __forceinline__ void mbar_wait_cluster(uint32_t mbar, unsigned parity) {
    asm volatile(
        "{\n\t.reg .pred P;\n\t"
        "WLOOP_%=:\n\t"
        "mbarrier.try_wait.parity.acquire.cluster.shared::cta.b64 P, [%0], %1, 0x989680;\n\t"
        "@P bra.uni WDONE_%=;\n\t"
        "bra.uni WLOOP_%=;\n\t"
        "WDONE_%=:\n\t}"
        :: "r"(mbar), "r"(parity) : "memory");
}

// ---------------- conv: [N,81,4,4] (x) [56,81,2,2] -> [N,504] (+pad to 512) --
__global__ void conv_kernel(const float* __restrict__ x, const float* __restrict__ Wc,
                            const float* __restrict__ bc) {
    __shared__ float xs[1296];
    const int n = blockIdx.x;
    const float4* xp = (const float4*)(x + (size_t)n * 1296);
    for (int i = threadIdx.x; i < 324; i += 64) ((float4*)xs)[i] = xp[i];
    __syncthreads();
    const int o = threadIdx.x;
    if (o < 56) {
        float acc[9];
        const float b = bc[o];
        #pragma unroll
        for (int p = 0; p < 9; p++) acc[p] = b;
        for (int i = 0; i < 81; i++) {
            float4 wv = *(const float4*)(Wc + o * 324 + i * 4);
            const float* xi = xs + i * 16;
            #pragma unroll
            for (int py = 0; py < 3; py++)
                #pragma unroll
                for (int px = 0; px < 3; px++) {
                    int p = py * 3 + px;
                    acc[p] += xi[py * 4 + px]     * wv.x + xi[py * 4 + px + 1]     * wv.y
                            + xi[(py+1) * 4 + px] * wv.z + xi[(py+1) * 4 + px + 1] * wv.w;
                }
        }
        float* op = g_conv + (size_t)n * 512 + o * 9;
        #pragma unroll
        for (int p = 0; p < 9; p++) op[p] = acc[p];
    } else {
        g_conv[(size_t)n * 512 + 448 + o] = 0.f;
    }
}

// ---------------- pad W_axis [512,504] -> [512,512] --------------------------
__global__ void pad_waxis(const float* __restrict__ W) {
    int idx = blockIdx.x * 256 + threadIdx.x;
    int r = idx >> 9, c = idx & 511;
    g_WaxPad[idx] = (c < 504) ? W[r * 504 + c] : 0.f;
}

// ---------------- SGEMM: C[M,N] (+)= A[M,K] * B[N,K]^T + bias[N] -------------
template <int ACC>
__global__ __launch_bounds__(256)
void sgemm_nt(const float* __restrict__ A, const float* __restrict__ B,
              const float* __restrict__ bias, float* __restrict__ C,
              int M, int N, int K) {
    __shared__ float As[8][128];
    __shared__ float Bs[8][128];
    const int tid = threadIdx.x;
    const int tx = tid & 15, ty = tid >> 4;
    const int lr = tid >> 1;
    const int lc = (tid & 1) << 2;
    const float* Ap = A + (size_t)(blockIdx.y * 128 + lr) * K + lc;
    const float* Bp = B + (size_t)(blockIdx.x * 128 + lr) * K + lc;
    float acc[8][8] = {};
    for (int k0 = 0; k0 < K; k0 += 8) {
        float4 av = *(const float4*)(Ap + k0);
        float4 bv = *(const float4*)(Bp + k0);
        __syncthreads();
        As[lc+0][lr] = av.x; As[lc+1][lr] = av.y; As[lc+2][lr] = av.z; As[lc+3][lr] = av.w;
        Bs[lc+0][lr] = bv.x; Bs[lc+1][lr] = bv.y; Bs[lc+2][lr] = bv.z; Bs[lc+3][lr] = bv.w;
        __syncthreads();
        #pragma unroll
        for (int k = 0; k < 8; k++) {
            float af[8], bf[8];
            *(float4*)(af)     = *(const float4*)&As[k][ty * 8];
            *(float4*)(af + 4) = *(const float4*)&As[k][ty * 8 + 4];
            *(float4*)(bf)     = *(const float4*)&Bs[k][tx * 8];
            *(float4*)(bf + 4) = *(const float4*)&Bs[k][tx * 8 + 4];
            #pragma unroll
            for (int i = 0; i < 8; i++)
                #pragma unroll
                for (int j = 0; j < 8; j++)
                    acc[i][j] += af[i] * bf[j];
        }
    }
    const int row0 = blockIdx.y * 128 + ty * 8;
    const int col0 = blockIdx.x * 128 + tx * 8;
    float bvals[8];
    #pragma unroll
    for (int j = 0; j < 8; j++) bvals[j] = bias[col0 + j];
    #pragma unroll
    for (int i = 0; i < 8; i++) {
        float* cp = C + (size_t)(row0 + i) * N + col0;
        #pragma unroll
        for (int j = 0; j < 8; j += 4) {
            float4 v;
            v.x = acc[i][j+0] + bvals[j+0];
            v.y = acc[i][j+1] + bvals[j+1];
            v.z = acc[i][j+2] + bvals[j+2];
            v.w = acc[i][j+3] + bvals[j+3];
            if (ACC) {
                float4 o = *(const float4*)(cp + j);
                v.x += o.x; v.y += o.y; v.z += o.z; v.w += o.w;
            }
            *(float4*)(cp + j) = v;
        }
    }
}

// ---------------- persistent GRU scan, 16-CTA cluster, DSMEM broadcast -------
// CTA c owns h[c*32 .. c*32+31] and 96 Whh rows {g*512 + c*32 + j}. Weights in
// registers (64 u64 = 128 regs/thread). Each step: GEMV from local padded h
// copy -> warp0 activations -> 16 lanes push the 32-float slice into all 16
// peers' SMEM (st.shared::cluster) + remote mbarrier.arrive.release.cluster.
// Double-buffered h + ping-pong mbarriers (parity in regs).
__global__ __launch_bounds__(NTHR, 1)
void scan_kernel(const float* __restrict__ Whh, const float* __restrict__ bhh, int steps) {
    // padded h: element e lives at (e/128)*132 + e%128 (windows start at banks 0,4,8,12)
    __shared__ float hbuf[2][528];
    __shared__ float hstage[32];
    __shared__ float gh_s[96];
    __shared__ alignas(8) unsigned long long mbar[2];

    const int c   = blockIdx.x;
    const int tid = threadIdx.x;
    const int w   = tid >> 5;
    const int l   = tid & 31;
    const int row = tid >> 2;          // 0..95
    const int seg = tid & 3;           // 0..3 (128-float windows)
    const int gate = row >> 5, j = row & 31;
    const int grow = gate * 512 + c * 32 + j;

    // weights -> registers (issue early, overlaps cluster setup)
    unsigned long long wq[64];
    {
        const ulonglong2* wp = (const ulonglong2*)(Whh + (size_t)grow * 512 + seg * 128);
        #pragma unroll
        for (int i = 0; i < 32; i++) { ulonglong2 t2 = wp[i]; wq[2*i] = t2.x; wq[2*i+1] = t2.y; }
    }
    const float bh = bhh[grow];

    if (tid == 0) {
        uint32_t mb = smem_u32(&mbar[0]);
        asm volatile("mbarrier.init.shared.b64 [%0], %1;" :: "r"(mb),     "r"(NCTA) : "memory");
        asm volatile("mbarrier.init.shared.b64 [%0], %1;" :: "r"(mb + 8), "r"(NCTA) : "memory");
    }
    for (int i = tid; i < 2 * 528; i += NTHR) ((float*)hbuf)[i] = 0.f;
    __syncthreads();
    asm volatile("barrier.cluster.arrive.aligned;" ::: "memory");
    asm volatile("barrier.cluster.wait.aligned;"   ::: "memory");

    // precomputed addresses
    const float* hb0p = &hbuf[0][0] + seg * 132;
    const float* hb1p = &hbuf[1][0] + seg * 132;
    const uint32_t slot_bytes = (uint32_t)(((c >> 2) * 132 + (c & 3) * 32) * 4);
    uint32_t rdst0 = 0, rdst1 = 0, rmb0 = 0, rmb1 = 0;
    if (w == 0 && l < NCTA) {
        uint32_t hb_loc = smem_u32(&hbuf[0][0]);
        rdst0 = mapa_u32(hb_loc + slot_bytes,        (uint32_t)l);
        rdst1 = mapa_u32(hb_loc + 528*4 + slot_bytes,(uint32_t)l);
        uint32_t mb_loc = smem_u32(&mbar[0]);
        rmb0  = mapa_u32(mb_loc,     (uint32_t)l);
        rmb1  = mapa_u32(mb_loc + 8, (uint32_t)l);
    }
    const uint32_t mb_self = smem_u32(&mbar[0]);

    float hreg = 0.f;
    unsigned par0 = 0, par1 = 0;

    // Gi prefetch (one step ahead, warp 0)
    float gi_r = 0.f, gi_z = 0.f, gi_n = 0.f;
    float gn_r = 0.f, gn_z = 0.f, gn_n = 0.f;
    if (w == 0) {
        const float* g0 = g_Gi + (size_t)c * 32 + l;
        gi_r = __ldcs(g0); gi_z = __ldcs(g0 + 512); gi_n = __ldcs(g0 + 1024);
    }

    for (int t = 0; t < steps; t++) {
        // issue next-step Gi loads before waiting (hide DRAM behind barrier+GEMV)
        if (w == 0 && (t + 1) < steps) {
            const float* gn = g_Gi + (size_t)(t + 1) * 1536 + c * 32 + l;
            gn_r = __ldcs(gn); gn_z = __ldcs(gn + 512); gn_n = __ldcs(gn + 1024);
        }
        // wait for h_t (t=0: local zeros, no wait)
        if (t > 0) {
            if (t & 1) { mbar_wait_cluster(mb_self + 8, par1); par1 ^= 1; }
            else       { mbar_wait_cluster(mb_self,     par0); par0 ^= 1; }
        }
        const float* hseg = (t & 1) ? hb1p : hb0p;

        // GEMV: dot(Whh[grow, seg*128 .. +128], h[seg*128 .. +128])
        unsigned long long a0 = 0ull, a1 = 0ull;
        #pragma unroll
        for (int i = 0; i < 32; i++) {
            ulonglong2 hv = *(const ulonglong2*)(hseg + i * 4);
            fma2(a0, wq[2*i],   hv.x);
            fma2(a1, wq[2*i+1], hv.y);
        }
        float2 f0 = unpack2(a0), f1 = unpack2(a1);
        float v = (f0.x + f0.y) + (f1.x + f1.y);
        v += __shfl_xor_sync(0xffffffffu, v, 1);
        v += __shfl_xor_sync(0xffffffffu, v, 2);
        if (seg == 0) gh_s[row] = v + bh;
        __syncthreads();                                   // gh ready

        if (w == 0) {
            float r = sigm(gi_r + gh_s[l]);
            float z = sigm(gi_z + gh_s[32 + l]);
            float n = tanh_acc(gi_n + r * gh_s[64 + l]);
            hreg = (1.f - z) * n + z * hreg;
            g_hs[(size_t)t * 512 + c * 32 + l] = hreg;     // fire-and-forget
            if ((t + 1) < steps) {
                hstage[l] = hreg;
                __syncwarp();
                if (l < NCTA) {
                    const float4* hs4 = (const float4*)hstage;
                    const uint32_t dst = ((t + 1) & 1) ? rdst1 : rdst0;
                    #pragma unroll
                    for (int i = 0; i < 8; i++) {
                        float4 hv = hs4[i];
                        asm volatile("st.shared::cluster.v4.f32 [%0], {%1,%2,%3,%4};"
                                     :: "r"(dst + 16u * i),
                                        "f"(hv.x), "f"(hv.y), "f"(hv.z), "f"(hv.w) : "memory");
                    }
                    const uint32_t rb = ((t + 1) & 1) ? rmb1 : rmb0;
                    asm volatile("mbarrier.arrive.release.cluster.shared::cluster.b64 _, [%0];"
                                 :: "r"(rb) : "memory");
                }
            }
            gi_r = gn_r; gi_z = gn_z; gi_n = gn_n;
        }
    }
}

// ---------------- decin = relu(feats + enc_final) ----------------------------
__global__ void decin_kernel() {
    int idx = blockIdx.x * 512 + threadIdx.x;
    const float4* f4 = (const float4*)g_feats;
    const float4* e4 = (const float4*)(g_hs + (size_t)8191 * 512);
    float4 f = f4[idx];
    float4 e = e4[idx & 127];
    float4 r;
    r.x = fmaxf(f.x + e.x, 0.f); r.y = fmaxf(f.y + e.y, 0.f);
    r.z = fmaxf(f.z + e.z, 0.f); r.w = fmaxf(f.w + e.w, 0.f);
    ((float4*)g_decin)[idx] = r;
}

// ---------------- out = sigmoid(hs @ W_out^T + b_out) ------------------------
__global__ void out_kernel(const float* __restrict__ Wout, const float* __restrict__ bout,
                           float* __restrict__ out) {
    int row = blockIdx.x * 8 + (threadIdx.x >> 5);
    int l = threadIdx.x & 31;
    const float4* h4 = (const float4*)(g_hs + (size_t)row * 512);
    const float4* w4 = (const float4*)Wout;
    float s = 0.f;
    #pragma unroll
    for (int k = 0; k < 4; k++) {
        float4 h = h4[l + 32 * k], w = w4[l + 32 * k];
        s += h.x * w.x + h.y * w.y + h.z * w.z + h.w * w.w;
    }
    #pragma unroll
    for (int o = 16; o > 0; o >>= 1) s += __shfl_xor_sync(0xffffffffu, s, o);
    if (l == 0) out[row] = sigm(s + bout[0]);
}

// ---------------- launch ------------------------------------------------------
static void launch_scan(const float* Whh, const float* bhh, int steps) {
    static int attr_done = 0;
    if (!attr_done) {
        cudaFuncSetAttribute(scan_kernel, cudaFuncAttributeNonPortableClusterSizeAllowed, 1);
        attr_done = 1;
    }
    cudaLaunchConfig_t cfg = {};
    cfg.gridDim  = dim3(NCTA, 1, 1);
    cfg.blockDim = dim3(NTHR, 1, 1);
    cfg.dynamicSmemBytes = 0;
    cfg.stream = 0;
    cudaLaunchAttribute attrs[1];
    attrs[0].id = cudaLaunchAttributeClusterDimension;
    attrs[0].val.clusterDim.x = NCTA;
    attrs[0].val.clusterDim.y = 1;
    attrs[0].val.clusterDim.z = 1;
    cfg.attrs = attrs;
    cfg.numAttrs = 1;
    cudaLaunchKernelEx(&cfg, scan_kernel, Whh, bhh, steps);
}

extern "C" void kernel_launch(void* const* d_in, const int* in_sizes, int n_in,
                              void* d_out, int out_size) {
    const float* boxes_feature   = (const float*)d_in[0];
    const float* boxes_box_score = (const float*)d_in[1];
    const float* W_app  = (const float*)d_in[2];
    const float* b_app  = (const float*)d_in[3];
    const float* W_conv = (const float*)d_in[4];
    const float* b_conv = (const float*)d_in[5];
    const float* W_axis = (const float*)d_in[6];
    const float* b_axis = (const float*)d_in[7];
    const float* Wih_e  = (const float*)d_in[8];
    const float* Whh_e  = (const float*)d_in[9];
    const float* bih_e  = (const float*)d_in[10];
    const float* bhh_e  = (const float*)d_in[11];
    const float* Wih_d  = (const float*)d_in[12];
    const float* Whh_d  = (const float*)d_in[13];
    const float* bih_d  = (const float*)d_in[14];
    const float* bhh_d  = (const float*)d_in[15];
    const float* W_out  = (const float*)d_in[16];
    const float* b_out  = (const float*)d_in[17];
    float* out = (float*)d_out;

    conv_kernel<<<NPROP, 64>>>(boxes_box_score, W_conv, b_conv);
    pad_waxis<<<1024, 256>>>(W_axis);

    float* feats = nullptr; cudaGetSymbolAddress((void**)&feats, g_feats);
    float* convp = nullptr; cudaGetSymbolAddress((void**)&convp, g_conv);
    float* waxp  = nullptr; cudaGetSymbolAddress((void**)&waxp,  g_WaxPad);
    float* gi    = nullptr; cudaGetSymbolAddress((void**)&gi,    g_Gi);
    float* decin = nullptr; cudaGetSymbolAddress((void**)&decin, g_decin);

    sgemm_nt<0><<<dim3(4, 64), 256>>>(boxes_feature, W_app, b_app, feats, NPROP, 512, 1024);
    sgemm_nt<1><<<dim3(4, 64), 256>>>(convp, waxp, b_axis, feats, NPROP, 512, 512);

    // encoder
    sgemm_nt<0><<<dim3(12, 64), 256>>>(feats, Wih_e, bih_e, gi, NPROP, 1536, 512);
    launch_scan(Whh_e, bhh_e, NPROP);

    // decoder
    decin_kernel<<<2048, 512>>>();
    sgemm_nt<0><<<dim3(12, 64), 256>>>(decin, Wih_d, bih_d, gi, NPROP, 1536, 512);
    launch_scan(Whh_d, bhh_d, NPROP);

    out_kernel<<<1024, 256>>>(W_out, b_out, out);
}